// round 13
// baseline (speedup 1.0000x reference)
#include <cuda_runtime.h>
#include <cuda.h>
#include <math.h>
#include <stdint.h>

// Allpass biquad over [B, 1, T] fp32, T = 480000.
// R13: TMA bulk-tensor pipeline, 6-stage ring of 4096-sample chunks with
// prefetch depth 4 and static scheduling. Each chunk: ONE 3D TMA load
// (box [32 floats, 128 segs, 1 row], SW128) + ONE TMA store. 256 threads
// each filter an independent 16-sample half-segment after a 16-sample
// warm-up (poles decay 0.414/sample -> truncation ~7.5e-7). Store-drain is
// 3 iterations off the critical path (wait_group 2 on a ring of 6).

#define T_LEN        480000
#define ROWS_CHUNK   128                 // 32-float rows per chunk
#define CHUNK        (32 * ROWS_CHUNK)   // 4096 samples
#define SEGS_PER_ROW (T_LEN / 32)        // 15000
#define CHUNKS_PER_ROW 118               // 117 full + 24-row tail
#define NTHREADS     256
#define GRID_BLOCKS  296                 // 148 SMs * 2 blocks
#define NSTAGE       6
#define PF_DEPTH     4
#define STAGE_BYTES  17408               // 16KB main + 128B tail, 1KB-aligned
#define TAIL_OFF_B   16384
#define CTRL_OFF_B   (NSTAGE * STAGE_BYTES)   // 104448
#define SMEM_BYTES   (CTRL_OFF_B + 64)
#define EXPECT_BYTES (16384u + 128u)

__device__ __forceinline__ uint32_t smem_u32(const void* p) {
    return (uint32_t)__cvta_generic_to_shared(p);
}

__global__ void __launch_bounds__(NTHREADS, 2)
allpass_kernel(const __grid_constant__ CUtensorMap mx,
               const __grid_constant__ CUtensorMap mtail,
               const __grid_constant__ CUtensorMap my_map,
               float b0, float b1, float b2, float a1, float a2,
               int total_chunks)
{
    extern __shared__ __align__(1024) unsigned char smem[];
    const int tid = threadIdx.x;
    const uint32_t mbar0 = smem_u32(smem + CTRL_OFF_B);

    if (tid == 0) {
        asm volatile("prefetch.tensormap [%0];" :: "l"((const void*)&mx));
        asm volatile("prefetch.tensormap [%0];" :: "l"((const void*)&mtail));
        asm volatile("prefetch.tensormap [%0];" :: "l"((const void*)&my_map));
        #pragma unroll
        for (int s = 0; s < NSTAGE; s++)
            asm volatile("mbarrier.init.shared.b64 [%0], 1;"
                         :: "r"(mbar0 + s * 8) : "memory");
    }
    __syncthreads();

    // tid0: expect_tx + main box + 32-float history box. Negative/past-end
    // seg coords zero-fill, exactly modeling the zero initial state.
    auto issue_load = [&](int idx, int s) {
        const int row  = idx / CHUNKS_PER_ROW;
        const int ch   = idx % CHUNKS_PER_ROW;
        const int seg0 = ch * ROWS_CHUNK;
        const uint32_t mb = mbar0 + s * 8;
        asm volatile("mbarrier.arrive.expect_tx.shared.b64 _, [%0], %1;"
                     :: "r"(mb), "r"(EXPECT_BYTES) : "memory");
        const uint32_t dst = smem_u32(smem + s * STAGE_BYTES);
        asm volatile(
            "cp.async.bulk.tensor.3d.shared::cta.global.tile"
            ".mbarrier::complete_tx::bytes [%0], [%1, {%2, %3, %4}], [%5];"
            :: "r"(dst), "l"((const void*)&mx),
               "r"(0), "r"(seg0), "r"(row), "r"(mb) : "memory");
        const uint32_t dstt = smem_u32(smem + s * STAGE_BYTES + TAIL_OFF_B);
        asm volatile(
            "cp.async.bulk.tensor.3d.shared::cta.global.tile"
            ".mbarrier::complete_tx::bytes [%0], [%1, {%2, %3, %4}], [%5];"
            :: "r"(dstt), "l"((const void*)&mtail),
               "r"(0), "r"(seg0 - 1), "r"(row), "r"(mb) : "memory");
    };

    // static schedule: local iteration k -> chunk blockIdx.x + k*gridDim
    auto idx_of = [&](int k) { return (int)blockIdx.x + k * GRID_BLOCKS; };

    if (tid == 0) {
        #pragma unroll
        for (int d = 0; d < PF_DEPTH; d++)
            if (idx_of(d) < total_chunks) issue_load(idx_of(d), d);
    }

    for (int k = 0; idx_of(k) < total_chunks; k++) {
        const int cs = k % NSTAGE;
        const unsigned par = (unsigned)(k / NSTAGE) & 1u;

        // wait for this stage's TMA load (deep prefetch -> usually fast-path)
        asm volatile(
            "{\n\t.reg .pred P;\n"
            "WAIT_%=:\n\t"
            "mbarrier.try_wait.parity.acquire.cta.shared::cta.b64 "
            "P, [%0], %1, 0x989680;\n\t"
            "@P bra DONE_%=;\n\t"
            "bra WAIT_%=;\n"
            "DONE_%=:\n\t}"
            :: "r"(mbar0 + cs * 8), "r"(par) : "memory");

        const int idx  = idx_of(k);
        const int seg0 = (idx % CHUNKS_PER_ROW) * ROWS_CHUNK;
        const int n_half = min(2 * ROWS_CHUNK, (SEGS_PER_ROW - seg0) * 2);
        char* sb = (char*)(smem + cs * STAGE_BYTES);

        if (tid < n_half) {
            const int r = tid >> 1;      // 32-float row in the tile
            const int h = tid & 1;       // which 16-float half

            // ---- warm-up: the 16 floats preceding this half ----
            float wv[16];
            if (tid == 0) {
                const float* tl = (const float*)(sb + TAIL_OFF_B);
                #pragma unroll
                for (int q = 0; q < 4; q++)
                    *reinterpret_cast<float4*>(&wv[q * 4]) =
                        *reinterpret_cast<const float4*>(tl + 16 + q * 4);
            } else {
                const int wr = h ? r : r - 1;
                const int wh = h ? 0 : 1;
                const int sw = (wr & 7) * 16;
                #pragma unroll
                for (int q = 0; q < 4; q++)
                    *reinterpret_cast<float4*>(&wv[q * 4]) =
                        *reinterpret_cast<const float4*>(
                            sb + wr * 128 + ((wh * 64 + q * 16) ^ sw));
            }
            float y1 = 0.0f, y2 = 0.0f, x1 = 0.0f, x2 = 0.0f;
            #pragma unroll
            for (int kk = 0; kk < 16; kk++) {
                const float xv = wv[kk];
                const float yn = b0 * xv + b1 * x1 + b2 * x2
                               - a1 * y1 - a2 * y2;
                y2 = y1; y1 = yn; x2 = x1; x1 = xv;
            }

            // ---- 16 output samples in place (SW128-aware) ----
            const int sw = (r & 7) * 16;
            #pragma unroll
            for (int q = 0; q < 4; q++) {
                float4* p = reinterpret_cast<float4*>(
                    sb + r * 128 + ((h * 64 + q * 16) ^ sw));
                float4 v = *p;
                float yn;
                yn = b0 * v.x + b1 * x1 + b2 * x2 - a1 * y1 - a2 * y2;
                y2 = y1; y1 = yn; x2 = x1; x1 = v.x; v.x = yn;
                yn = b0 * v.y + b1 * x1 + b2 * x2 - a1 * y1 - a2 * y2;
                y2 = y1; y1 = yn; x2 = x1; x1 = v.y; v.y = yn;
                yn = b0 * v.z + b1 * x1 + b2 * x2 - a1 * y1 - a2 * y2;
                y2 = y1; y1 = yn; x2 = x1; x1 = v.z; v.z = yn;
                yn = b0 * v.w + b1 * x1 + b2 * x2 - a1 * y1 - a2 * y2;
                y2 = y1; y1 = yn; x2 = x1; x1 = v.w; v.w = yn;
                *p = v;
            }
        }
        __syncthreads();

        if (tid == 0) {
            // store current chunk (TMA clips OOB rows on the tail chunk)
            asm volatile("fence.proxy.async.shared::cta;" ::: "memory");
            const int row = idx / CHUNKS_PER_ROW;
            const uint32_t src = smem_u32(smem + cs * STAGE_BYTES);
            asm volatile(
                "cp.async.bulk.tensor.3d.global.shared::cta.tile.bulk_group "
                "[%0, {%1, %2, %3}], [%4];"
                :: "l"((const void*)&my_map),
                   "r"(0), "r"(seg0), "r"(row), "r"(src) : "memory");
            asm volatile("cp.async.bulk.commit_group;" ::: "memory");

            // prefetch k+PF_DEPTH into stage (k+PF_DEPTH)%6; its previous
            // occupant was stored at k-2, guaranteed drained by wait_group 2
            // (pending <= stores k, k-1).
            asm volatile("cp.async.bulk.wait_group 2;" ::: "memory");
            const int pidx = idx_of(k + PF_DEPTH);
            if (pidx < total_chunks)
                issue_load(pidx, (k + PF_DEPTH) % NSTAGE);
        }
    }

    // drain outstanding TMA stores before the CTA (and its smem) retires
    if (tid == 0)
        asm volatile("cp.async.bulk.wait_group 0;" ::: "memory");
}

typedef CUresult (*EncFn)(CUtensorMap*, CUtensorMapDataType, cuuint32_t, void*,
                          const cuuint64_t*, const cuuint64_t*,
                          const cuuint32_t*, const cuuint32_t*,
                          CUtensorMapInterleave, CUtensorMapSwizzle,
                          CUtensorMapL2promotion, CUtensorMapFloatOOBfill);

extern "C" void kernel_launch(void* const* d_in, const int* in_sizes, int n_in,
                              void* d_out, int out_size)
{
    const float* x = (const float*)d_in[0];
    float* y = (float*)d_out;

    const int total = in_sizes[0];
    const int B = total / T_LEN;   // 64

    // Coefficients in float64 then cast, matching the numpy reference.
    const double w0    = 2.0 * M_PI * 4000.0 / 16000.0;
    const double alpha = sin(w0) / (2.0 * 0.707);
    const double cw0   = cos(w0);
    const double a0d   = 1.0 + alpha;
    const float b0 = (float)((1.0 - alpha) / a0d);
    const float b1 = (float)((-2.0 * cw0) / a0d);
    const float b2 = (float)((1.0 + alpha) / a0d);
    const float a1 = (float)((-2.0 * cw0) / a0d);
    const float a2 = (float)((1.0 - alpha) / a0d);

    EncFn enc = nullptr;
    {
        void* p = nullptr;
        cudaDriverEntryPointQueryResult st;
        cudaGetDriverEntryPointByVersion("cuTensorMapEncodeTiled", &p, 12000,
                                         cudaEnableDefault, &st);
        enc = (EncFn)p;
    }

    // x/y viewed as [32 floats][15000 segs][B rows]
    cuuint64_t dims[3]    = {32, (cuuint64_t)SEGS_PER_ROW, (cuuint64_t)B};
    cuuint64_t strides[2] = {32 * 4, (cuuint64_t)T_LEN * 4};
    cuuint32_t box_main[3] = {32, ROWS_CHUNK, 1};
    cuuint32_t box_tail[3] = {32, 1, 1};
    cuuint32_t estr[3]     = {1, 1, 1};

    CUtensorMap mx, mtail, my_map;
    enc(&mx, CU_TENSOR_MAP_DATA_TYPE_FLOAT32, 3, (void*)x, dims, strides,
        box_main, estr, CU_TENSOR_MAP_INTERLEAVE_NONE,
        CU_TENSOR_MAP_SWIZZLE_128B, CU_TENSOR_MAP_L2_PROMOTION_L2_128B,
        CU_TENSOR_MAP_FLOAT_OOB_FILL_NONE);
    enc(&mtail, CU_TENSOR_MAP_DATA_TYPE_FLOAT32, 3, (void*)x, dims, strides,
        box_tail, estr, CU_TENSOR_MAP_INTERLEAVE_NONE,
        CU_TENSOR_MAP_SWIZZLE_NONE, CU_TENSOR_MAP_L2_PROMOTION_L2_128B,
        CU_TENSOR_MAP_FLOAT_OOB_FILL_NONE);
    enc(&my_map, CU_TENSOR_MAP_DATA_TYPE_FLOAT32, 3, (void*)y, dims, strides,
        box_main, estr, CU_TENSOR_MAP_INTERLEAVE_NONE,
        CU_TENSOR_MAP_SWIZZLE_128B, CU_TENSOR_MAP_L2_PROMOTION_L2_128B,
        CU_TENSOR_MAP_FLOAT_OOB_FILL_NONE);

    static bool attr_set = false;
    if (!attr_set) {
        cudaFuncSetAttribute(allpass_kernel,
                             cudaFuncAttributeMaxDynamicSharedMemorySize,
                             SMEM_BYTES);
        attr_set = true;
    }

    const int total_chunks = B * CHUNKS_PER_ROW;   // 7552

    allpass_kernel<<<GRID_BLOCKS, NTHREADS, SMEM_BYTES>>>(
        mx, mtail, my_map, b0, b1, b2, a1, a2, total_chunks);
}

// round 14
// speedup vs baseline: 1.0921x; 1.0921x over previous
#include <cuda_runtime.h>
#include <cuda.h>
#include <math.h>
#include <stdint.h>

// Allpass biquad over [B, 1, T] fp32, T = 480000.
// R14: one 4096-sample chunk per (short-lived) block. ONE 3D TMA load
// (box [32 floats, 128 segs], SW128, + 128B history box) -> 256 threads each
// filter an independent 16-sample half-segment after a 16-sample warm-up
// (poles decay 0.414/sample -> truncation ~7.5e-7) -> ONE TMA store.
// Cross-chunk overlap comes from 8 co-resident blocks per SM + CLC refill,
// not from an in-kernel ring: no persistence, no counters, minimal ramp.

#define T_LEN        480000
#define ROWS_CHUNK   128                 // 32-float rows per chunk
#define SEGS_PER_ROW (T_LEN / 32)        // 15000
#define CHUNKS_PER_ROW 118               // 117 full + 24-row tail
#define NTHREADS     256
#define EXPECT_BYTES (16384u + 128u)

__device__ __forceinline__ uint32_t smem_u32(const void* p) {
    return (uint32_t)__cvta_generic_to_shared(p);
}

__global__ void __launch_bounds__(NTHREADS, 8)
allpass_kernel(const __grid_constant__ CUtensorMap mx,
               const __grid_constant__ CUtensorMap mtail,
               const __grid_constant__ CUtensorMap my_map,
               float b0, float b1, float b2, float a1, float a2)
{
    __shared__ __align__(1024) unsigned char sb[16384];   // main tile (SW128)
    __shared__ __align__(128)  float tail[32];            // 32-float history
    __shared__ __align__(8)    unsigned long long mbar;

    const int tid = threadIdx.x;
    const int ch  = blockIdx.x;          // chunk within row
    const int row = blockIdx.y;          // batch row
    const int seg0 = ch * ROWS_CHUNK;
    const uint32_t mb = smem_u32(&mbar);

    if (tid == 0)
        asm volatile("mbarrier.init.shared.b64 [%0], 1;" :: "r"(mb) : "memory");
    __syncthreads();

    if (tid == 0) {
        // expect_tx + main box + history box. Negative / past-end segment
        // coords zero-fill, exactly modeling the zero initial state.
        asm volatile("mbarrier.arrive.expect_tx.shared.b64 _, [%0], %1;"
                     :: "r"(mb), "r"(EXPECT_BYTES) : "memory");
        asm volatile(
            "cp.async.bulk.tensor.3d.shared::cta.global.tile"
            ".mbarrier::complete_tx::bytes [%0], [%1, {%2, %3, %4}], [%5];"
            :: "r"(smem_u32(sb)), "l"((const void*)&mx),
               "r"(0), "r"(seg0), "r"(row), "r"(mb) : "memory");
        asm volatile(
            "cp.async.bulk.tensor.3d.shared::cta.global.tile"
            ".mbarrier::complete_tx::bytes [%0], [%1, {%2, %3, %4}], [%5];"
            :: "r"(smem_u32(tail)), "l"((const void*)&mtail),
               "r"(0), "r"(seg0 - 1), "r"(row), "r"(mb) : "memory");
    }

    // wait for the TMA load (parity 0)
    asm volatile(
        "{\n\t.reg .pred P;\n"
        "WAIT_%=:\n\t"
        "mbarrier.try_wait.parity.acquire.cta.shared::cta.b64 "
        "P, [%0], 0, 0x989680;\n\t"
        "@P bra DONE_%=;\n\t"
        "bra WAIT_%=;\n"
        "DONE_%=:\n\t}"
        :: "r"(mb) : "memory");

    const int n_half = min(2 * ROWS_CHUNK, (SEGS_PER_ROW - seg0) * 2);

    if (tid < n_half) {
        const int r = tid >> 1;          // 32-float row in the tile
        const int h = tid & 1;           // which 16-float half

        // ---- warm-up: the 16 floats preceding this half ----
        float wv[16];
        if (tid == 0) {
            #pragma unroll
            for (int q = 0; q < 4; q++)
                *reinterpret_cast<float4*>(&wv[q * 4]) =
                    *reinterpret_cast<const float4*>(tail + 16 + q * 4);
        } else {
            const int wr = h ? r : r - 1;
            const int wh = h ? 0 : 1;
            const int sw = (wr & 7) * 16;
            #pragma unroll
            for (int q = 0; q < 4; q++)
                *reinterpret_cast<float4*>(&wv[q * 4]) =
                    *reinterpret_cast<const float4*>(
                        (const char*)sb + wr * 128 + ((wh * 64 + q * 16) ^ sw));
        }
        float y1 = 0.0f, y2 = 0.0f, x1 = 0.0f, x2 = 0.0f;
        #pragma unroll
        for (int kk = 0; kk < 16; kk++) {
            const float xv = wv[kk];
            const float yn = b0 * xv + b1 * x1 + b2 * x2 - a1 * y1 - a2 * y2;
            y2 = y1; y1 = yn; x2 = x1; x1 = xv;
        }

        // ---- 16 output samples in place (SW128-aware) ----
        const int sw = (r & 7) * 16;
        #pragma unroll
        for (int q = 0; q < 4; q++) {
            float4* p = reinterpret_cast<float4*>(
                (char*)sb + r * 128 + ((h * 64 + q * 16) ^ sw));
            float4 v = *p;
            float yn;
            yn = b0 * v.x + b1 * x1 + b2 * x2 - a1 * y1 - a2 * y2;
            y2 = y1; y1 = yn; x2 = x1; x1 = v.x; v.x = yn;
            yn = b0 * v.y + b1 * x1 + b2 * x2 - a1 * y1 - a2 * y2;
            y2 = y1; y1 = yn; x2 = x1; x1 = v.y; v.y = yn;
            yn = b0 * v.z + b1 * x1 + b2 * x2 - a1 * y1 - a2 * y2;
            y2 = y1; y1 = yn; x2 = x1; x1 = v.z; v.z = yn;
            yn = b0 * v.w + b1 * x1 + b2 * x2 - a1 * y1 - a2 * y2;
            y2 = y1; y1 = yn; x2 = x1; x1 = v.w; v.w = yn;
            *p = v;
        }
    }
    __syncthreads();

    if (tid == 0) {
        // TMA store (clips OOB rows on the tail chunk); drain before retire
        asm volatile("fence.proxy.async.shared::cta;" ::: "memory");
        asm volatile(
            "cp.async.bulk.tensor.3d.global.shared::cta.tile.bulk_group "
            "[%0, {%1, %2, %3}], [%4];"
            :: "l"((const void*)&my_map),
               "r"(0), "r"(seg0), "r"(row), "r"(smem_u32(sb)) : "memory");
        asm volatile("cp.async.bulk.commit_group;" ::: "memory");
        asm volatile("cp.async.bulk.wait_group 0;" ::: "memory");
    }
}

typedef CUresult (*EncFn)(CUtensorMap*, CUtensorMapDataType, cuuint32_t, void*,
                          const cuuint64_t*, const cuuint64_t*,
                          const cuuint32_t*, const cuuint32_t*,
                          CUtensorMapInterleave, CUtensorMapSwizzle,
                          CUtensorMapL2promotion, CUtensorMapFloatOOBfill);

extern "C" void kernel_launch(void* const* d_in, const int* in_sizes, int n_in,
                              void* d_out, int out_size)
{
    const float* x = (const float*)d_in[0];
    float* y = (float*)d_out;

    const int total = in_sizes[0];
    const int B = total / T_LEN;   // 64

    // Coefficients in float64 then cast, matching the numpy reference.
    const double w0    = 2.0 * M_PI * 4000.0 / 16000.0;
    const double alpha = sin(w0) / (2.0 * 0.707);
    const double cw0   = cos(w0);
    const double a0d   = 1.0 + alpha;
    const float b0 = (float)((1.0 - alpha) / a0d);
    const float b1 = (float)((-2.0 * cw0) / a0d);
    const float b2 = (float)((1.0 + alpha) / a0d);
    const float a1 = (float)((-2.0 * cw0) / a0d);
    const float a2 = (float)((1.0 - alpha) / a0d);

    EncFn enc = nullptr;
    {
        void* p = nullptr;
        cudaDriverEntryPointQueryResult st;
        cudaGetDriverEntryPointByVersion("cuTensorMapEncodeTiled", &p, 12000,
                                         cudaEnableDefault, &st);
        enc = (EncFn)p;
    }

    // x/y viewed as [32 floats][15000 segs][B rows]
    cuuint64_t dims[3]    = {32, (cuuint64_t)SEGS_PER_ROW, (cuuint64_t)B};
    cuuint64_t strides[2] = {32 * 4, (cuuint64_t)T_LEN * 4};
    cuuint32_t box_main[3] = {32, ROWS_CHUNK, 1};
    cuuint32_t box_tail[3] = {32, 1, 1};
    cuuint32_t estr[3]     = {1, 1, 1};

    CUtensorMap mx, mtail, my_map;
    enc(&mx, CU_TENSOR_MAP_DATA_TYPE_FLOAT32, 3, (void*)x, dims, strides,
        box_main, estr, CU_TENSOR_MAP_INTERLEAVE_NONE,
        CU_TENSOR_MAP_SWIZZLE_128B, CU_TENSOR_MAP_L2_PROMOTION_L2_128B,
        CU_TENSOR_MAP_FLOAT_OOB_FILL_NONE);
    enc(&mtail, CU_TENSOR_MAP_DATA_TYPE_FLOAT32, 3, (void*)x, dims, strides,
        box_tail, estr, CU_TENSOR_MAP_INTERLEAVE_NONE,
        CU_TENSOR_MAP_SWIZZLE_NONE, CU_TENSOR_MAP_L2_PROMOTION_L2_128B,
        CU_TENSOR_MAP_FLOAT_OOB_FILL_NONE);
    enc(&my_map, CU_TENSOR_MAP_DATA_TYPE_FLOAT32, 3, (void*)y, dims, strides,
        box_main, estr, CU_TENSOR_MAP_INTERLEAVE_NONE,
        CU_TENSOR_MAP_SWIZZLE_128B, CU_TENSOR_MAP_L2_PROMOTION_L2_128B,
        CU_TENSOR_MAP_FLOAT_OOB_FILL_NONE);

    dim3 grid(CHUNKS_PER_ROW, B);   // 118 x 64 = 7552 blocks
    allpass_kernel<<<grid, NTHREADS>>>(mx, mtail, my_map,
                                       b0, b1, b2, a1, a2);
}

// round 15
// speedup vs baseline: 1.1091x; 1.0156x over previous
#include <cuda_runtime.h>
#include <cuda.h>
#include <math.h>
#include <stdint.h>

// Allpass biquad over [B, 1, T] fp32, T = 480000.
// R15 = R14 at half granularity: one 2048-sample chunk per 128-thread block
// (16 blocks/SM). ONE 3D TMA load (box [32 floats, 64 segs], SW128, + 128B
// history box) -> each thread filters an independent 16-sample half-segment
// after a 16-sample warm-up (poles decay 0.414/sample -> truncation ~7.5e-7)
// -> ONE TMA store. Cross-chunk overlap via 16 co-resident blocks + CLC.

#define T_LEN        480000
#define ROWS_CHUNK   64                  // 32-float rows per chunk
#define SEGS_PER_ROW (T_LEN / 32)        // 15000
#define CHUNKS_PER_ROW 235               // 234 full + 24-row tail
#define NTHREADS     128
#define EXPECT_BYTES (8192u + 128u)

__device__ __forceinline__ uint32_t smem_u32(const void* p) {
    return (uint32_t)__cvta_generic_to_shared(p);
}

__global__ void __launch_bounds__(NTHREADS, 16)
allpass_kernel(const __grid_constant__ CUtensorMap mx,
               const __grid_constant__ CUtensorMap mtail,
               const __grid_constant__ CUtensorMap my_map,
               float b0, float b1, float b2, float a1, float a2)
{
    __shared__ __align__(1024) unsigned char sb[8192];    // main tile (SW128)
    __shared__ __align__(128)  float tail[32];            // 32-float history
    __shared__ __align__(8)    unsigned long long mbar;

    const int tid = threadIdx.x;
    const int ch  = blockIdx.x;          // chunk within row
    const int row = blockIdx.y;          // batch row
    const int seg0 = ch * ROWS_CHUNK;
    const uint32_t mb = smem_u32(&mbar);

    if (tid == 0)
        asm volatile("mbarrier.init.shared.b64 [%0], 1;" :: "r"(mb) : "memory");
    __syncthreads();

    if (tid == 0) {
        // expect_tx + main box + history box. Negative / past-end segment
        // coords zero-fill, exactly modeling the zero initial state.
        asm volatile("mbarrier.arrive.expect_tx.shared.b64 _, [%0], %1;"
                     :: "r"(mb), "r"(EXPECT_BYTES) : "memory");
        asm volatile(
            "cp.async.bulk.tensor.3d.shared::cta.global.tile"
            ".mbarrier::complete_tx::bytes [%0], [%1, {%2, %3, %4}], [%5];"
            :: "r"(smem_u32(sb)), "l"((const void*)&mx),
               "r"(0), "r"(seg0), "r"(row), "r"(mb) : "memory");
        asm volatile(
            "cp.async.bulk.tensor.3d.shared::cta.global.tile"
            ".mbarrier::complete_tx::bytes [%0], [%1, {%2, %3, %4}], [%5];"
            :: "r"(smem_u32(tail)), "l"((const void*)&mtail),
               "r"(0), "r"(seg0 - 1), "r"(row), "r"(mb) : "memory");
    }

    // wait for the TMA load (parity 0)
    asm volatile(
        "{\n\t.reg .pred P;\n"
        "WAIT_%=:\n\t"
        "mbarrier.try_wait.parity.acquire.cta.shared::cta.b64 "
        "P, [%0], 0, 0x989680;\n\t"
        "@P bra DONE_%=;\n\t"
        "bra WAIT_%=;\n"
        "DONE_%=:\n\t}"
        :: "r"(mb) : "memory");

    const int n_half = min(2 * ROWS_CHUNK, (SEGS_PER_ROW - seg0) * 2);

    if (tid < n_half) {
        const int r = tid >> 1;          // 32-float row in the tile
        const int h = tid & 1;           // which 16-float half

        // ---- warm-up: the 16 floats preceding this half ----
        float wv[16];
        if (tid == 0) {
            #pragma unroll
            for (int q = 0; q < 4; q++)
                *reinterpret_cast<float4*>(&wv[q * 4]) =
                    *reinterpret_cast<const float4*>(tail + 16 + q * 4);
        } else {
            const int wr = h ? r : r - 1;
            const int wh = h ? 0 : 1;
            const int sw = (wr & 7) * 16;
            #pragma unroll
            for (int q = 0; q < 4; q++)
                *reinterpret_cast<float4*>(&wv[q * 4]) =
                    *reinterpret_cast<const float4*>(
                        (const char*)sb + wr * 128 + ((wh * 64 + q * 16) ^ sw));
        }
        float y1 = 0.0f, y2 = 0.0f, x1 = 0.0f, x2 = 0.0f;
        #pragma unroll
        for (int kk = 0; kk < 16; kk++) {
            const float xv = wv[kk];
            const float yn = b0 * xv + b1 * x1 + b2 * x2 - a1 * y1 - a2 * y2;
            y2 = y1; y1 = yn; x2 = x1; x1 = xv;
        }

        // ---- 16 output samples in place (SW128-aware) ----
        const int sw = (r & 7) * 16;
        #pragma unroll
        for (int q = 0; q < 4; q++) {
            float4* p = reinterpret_cast<float4*>(
                (char*)sb + r * 128 + ((h * 64 + q * 16) ^ sw));
            float4 v = *p;
            float yn;
            yn = b0 * v.x + b1 * x1 + b2 * x2 - a1 * y1 - a2 * y2;
            y2 = y1; y1 = yn; x2 = x1; x1 = v.x; v.x = yn;
            yn = b0 * v.y + b1 * x1 + b2 * x2 - a1 * y1 - a2 * y2;
            y2 = y1; y1 = yn; x2 = x1; x1 = v.y; v.y = yn;
            yn = b0 * v.z + b1 * x1 + b2 * x2 - a1 * y1 - a2 * y2;
            y2 = y1; y1 = yn; x2 = x1; x1 = v.z; v.z = yn;
            yn = b0 * v.w + b1 * x1 + b2 * x2 - a1 * y1 - a2 * y2;
            y2 = y1; y1 = yn; x2 = x1; x1 = v.w; v.w = yn;
            *p = v;
        }
    }
    __syncthreads();

    if (tid == 0) {
        // TMA store (clips OOB rows on the tail chunk); drain before retire
        asm volatile("fence.proxy.async.shared::cta;" ::: "memory");
        asm volatile(
            "cp.async.bulk.tensor.3d.global.shared::cta.tile.bulk_group "
            "[%0, {%1, %2, %3}], [%4];"
            :: "l"((const void*)&my_map),
               "r"(0), "r"(seg0), "r"(row), "r"(smem_u32(sb)) : "memory");
        asm volatile("cp.async.bulk.commit_group;" ::: "memory");
        asm volatile("cp.async.bulk.wait_group 0;" ::: "memory");
    }
}

typedef CUresult (*EncFn)(CUtensorMap*, CUtensorMapDataType, cuuint32_t, void*,
                          const cuuint64_t*, const cuuint64_t*,
                          const cuuint32_t*, const cuuint32_t*,
                          CUtensorMapInterleave, CUtensorMapSwizzle,
                          CUtensorMapL2promotion, CUtensorMapFloatOOBfill);

extern "C" void kernel_launch(void* const* d_in, const int* in_sizes, int n_in,
                              void* d_out, int out_size)
{
    const float* x = (const float*)d_in[0];
    float* y = (float*)d_out;

    const int total = in_sizes[0];
    const int B = total / T_LEN;   // 64

    // Coefficients in float64 then cast, matching the numpy reference.
    const double w0    = 2.0 * M_PI * 4000.0 / 16000.0;
    const double alpha = sin(w0) / (2.0 * 0.707);
    const double cw0   = cos(w0);
    const double a0d   = 1.0 + alpha;
    const float b0 = (float)((1.0 - alpha) / a0d);
    const float b1 = (float)((-2.0 * cw0) / a0d);
    const float b2 = (float)((1.0 + alpha) / a0d);
    const float a1 = (float)((-2.0 * cw0) / a0d);
    const float a2 = (float)((1.0 - alpha) / a0d);

    EncFn enc = nullptr;
    {
        void* p = nullptr;
        cudaDriverEntryPointQueryResult st;
        cudaGetDriverEntryPointByVersion("cuTensorMapEncodeTiled", &p, 12000,
                                         cudaEnableDefault, &st);
        enc = (EncFn)p;
    }

    // x/y viewed as [32 floats][15000 segs][B rows]
    cuuint64_t dims[3]    = {32, (cuuint64_t)SEGS_PER_ROW, (cuuint64_t)B};
    cuuint64_t strides[2] = {32 * 4, (cuuint64_t)T_LEN * 4};
    cuuint32_t box_main[3] = {32, ROWS_CHUNK, 1};
    cuuint32_t box_tail[3] = {32, 1, 1};
    cuuint32_t estr[3]     = {1, 1, 1};

    CUtensorMap mx, mtail, my_map;
    enc(&mx, CU_TENSOR_MAP_DATA_TYPE_FLOAT32, 3, (void*)x, dims, strides,
        box_main, estr, CU_TENSOR_MAP_INTERLEAVE_NONE,
        CU_TENSOR_MAP_SWIZZLE_128B, CU_TENSOR_MAP_L2_PROMOTION_L2_128B,
        CU_TENSOR_MAP_FLOAT_OOB_FILL_NONE);
    enc(&mtail, CU_TENSOR_MAP_DATA_TYPE_FLOAT32, 3, (void*)x, dims, strides,
        box_tail, estr, CU_TENSOR_MAP_INTERLEAVE_NONE,
        CU_TENSOR_MAP_SWIZZLE_NONE, CU_TENSOR_MAP_L2_PROMOTION_L2_128B,
        CU_TENSOR_MAP_FLOAT_OOB_FILL_NONE);
    enc(&my_map, CU_TENSOR_MAP_DATA_TYPE_FLOAT32, 3, (void*)y, dims, strides,
        box_main, estr, CU_TENSOR_MAP_INTERLEAVE_NONE,
        CU_TENSOR_MAP_SWIZZLE_128B, CU_TENSOR_MAP_L2_PROMOTION_L2_128B,
        CU_TENSOR_MAP_FLOAT_OOB_FILL_NONE);

    dim3 grid(CHUNKS_PER_ROW, B);   // 235 x 64 = 15040 blocks
    allpass_kernel<<<grid, NTHREADS>>>(mx, mtail, my_map,
                                       b0, b1, b2, a1, a2);
}